// round 16
// baseline (speedup 1.0000x reference)
#include <cuda_runtime.h>
#include <cuda_fp16.h>
#include <cstdint>
#include <cstddef>

// ---------------------------------------------------------------------------
// FFTAttention: fft2 -> GroupNorm -> QKV gemm -> attention -> proj -> ifft2
// b=8, c=256, h=w=32, n=2048, heads=4, ch=64.
// All matmul operands pre-packed to f16x2 once (weights, X, attention out);
// GEMMs: fp16 m16n8k16 2-term (A hi/lo x B hi). Attention: 1-MMA S (log2
// domain, ex2), 1-MMA PV, Q fragments hoisted to registers.
// ---------------------------------------------------------------------------

#define NTOK 2048

__device__ float    g_xr  [8 * 256 * NTOK];
__device__ uint32_t g_xp  [8 * 128 * NTOK];    // packed alpha*X, c-pairs [b][c2][n]
__device__ uint32_t g_ap  [8 * 128 * NTOK];    // packed attention out, c-pairs
__device__ uint32_t g_qp  [32 * 32 * NTOK];    // [hb][c2][t]
__device__ uint32_t g_kp  [32 * 32 * NTOK];    // [hb][c2][s]
__device__ uint32_t g_vp  [32 * 64 * (NTOK/2)];// [hb][c][s2]
__device__ uint32_t g_wqh [768 * 128];         // qkv_w blob [ob][kc][row][16]
__device__ uint32_t g_wql [768 * 128];
__device__ uint32_t g_wph [256 * 128];         // proj_w blob
__device__ uint32_t g_wpl [256 * 128];
__device__ float    g_proj[8 * 256 * NTOK];
__device__ float    g_alpha[8 * 256];
__device__ float    g_beta [8 * 256];
__device__ float    g_bb   [8 * 768];
__device__ float    g_stats[512];

#define QSCALE 0.1803368801111f   // ch^-0.5 * log2(e)

// ---------------- fp16 helpers ----------------
__device__ __forceinline__ uint32_t pack_h(float x0, float x1) {
    uint32_t h;
    asm("cvt.rn.f16x2.f32 %0, %1, %2;" : "=r"(h) : "f"(x1), "f"(x0));
    return h;
}
__device__ __forceinline__ void pack2(float x0, float x1, uint32_t& h, uint32_t& l) {
    asm("cvt.rn.f16x2.f32 %0, %1, %2;" : "=r"(h) : "f"(x1), "f"(x0));
    __half2 hh = *reinterpret_cast<const __half2*>(&h);
    float r0 = x0 - __low2float(hh);
    float r1 = x1 - __high2float(hh);
    asm("cvt.rn.f16x2.f32 %0, %1, %2;" : "=r"(l) : "f"(r1), "f"(r0));
}
__device__ __forceinline__ float ex2(float x) {
    float r;
    asm("ex2.approx.f32 %0, %1;" : "=f"(r) : "f"(x));
    return r;
}
__device__ __forceinline__ void mma16(float* d, const uint32_t* a, const uint32_t* b) {
    asm volatile(
        "mma.sync.aligned.m16n8k16.row.col.f32.f16.f16.f32 "
        "{%0,%1,%2,%3}, {%4,%5,%6,%7}, {%8,%9}, {%0,%1,%2,%3};\n"
        : "+f"(d[0]), "+f"(d[1]), "+f"(d[2]), "+f"(d[3])
        : "r"(a[0]), "r"(a[1]), "r"(a[2]), "r"(a[3]), "r"(b[0]), "r"(b[1]));
}

__global__ void k_zero_stats() { g_stats[threadIdx.x] = 0.f; }

// ---------------------------------------------------------------------------
// Forward FFT2 + groupnorm stats (one warp per (b,c) image)
// ---------------------------------------------------------------------------
__global__ void __launch_bounds__(32) k_fft(const float* __restrict__ x) {
    __shared__ float sr[32][33];
    __shared__ float si[32][33];
    __shared__ float2 tw[32];

    int img  = blockIdx.x;
    int lane = threadIdx.x;

    float sn, cs;
    __sincosf(-6.283185307179586f * (float)lane / 32.f, &sn, &cs);
    tw[lane] = make_float2(cs, sn);

    const float* xin = x + (size_t)img * 1024;
#pragma unroll
    for (int y = 0; y < 32; y++) sr[y][lane] = xin[y * 32 + lane];
    __syncwarp();

    float vr[32];
#pragma unroll
    for (int j = 0; j < 32; j++) vr[j] = sr[lane][j];
    __syncwarp();

    for (int k = 0; k < 32; k++) {
        float ar = 0.f, ai = 0.f;
#pragma unroll
        for (int j = 0; j < 32; j++) {
            float2 w = tw[(j * k) & 31];
            ar += vr[j] * w.x;
            ai += vr[j] * w.y;
        }
        sr[k][lane] = ar;
        si[k][lane] = ai;
    }
    __syncwarp();

    float cr[32], ci[32];
#pragma unroll
    for (int t = 0; t < 32; t++) { cr[t] = sr[lane][t]; ci[t] = si[lane][t]; }

    float* outp = g_xr + (size_t)img * NTOK;
    float sum = 0.f, ssq = 0.f;
    for (int k = 0; k < 32; k++) {
        float ar = 0.f, ai = 0.f;
#pragma unroll
        for (int j = 0; j < 32; j++) {
            float2 w = tw[(j * k) & 31];
            ar += cr[j] * w.x - ci[j] * w.y;
            ai += cr[j] * w.y + ci[j] * w.x;
        }
        outp[(k * 32 + lane) * 2 + 0] = ar;
        outp[(k * 32 + lane) * 2 + 1] = ai;
        sum += ar + ai;
        ssq += ar * ar + ai * ai;
    }

#pragma unroll
    for (int off = 16; off > 0; off >>= 1) {
        sum += __shfl_xor_sync(0xffffffffu, sum, off);
        ssq += __shfl_xor_sync(0xffffffffu, ssq, off);
    }
    if (lane == 0) {
        int b  = img >> 8;
        int ch = img & 255;
        int grp = b * 32 + (ch >> 3);
        atomicAdd(&g_stats[grp * 2 + 0], sum);
        atomicAdd(&g_stats[grp * 2 + 1], ssq);
    }
}

__global__ void k_prep_ab(const float* __restrict__ gn_w, const float* __restrict__ gn_b) {
    int b = blockIdx.x;
    int c = threadIdx.x;
    int grp = b * 32 + (c >> 3);
    float s0 = g_stats[grp * 2 + 0];
    float s1 = g_stats[grp * 2 + 1];
    float mean = s0 * (1.f / 16384.f);
    float var  = s1 * (1.f / 16384.f) - mean * mean;
    float rs   = rsqrtf(var + 1e-5f);
    float w = gn_w[c];
    g_alpha[b * 256 + c] = rs * w;
    g_beta [b * 256 + c] = gn_b[c] - mean * rs * w;
}

__global__ void __launch_bounds__(256) k_prep_bb(const float* __restrict__ qkv_w,
                                                 const float* __restrict__ qkv_b) {
    int w = (blockIdx.x * 256 + threadIdx.x) >> 5;
    int lane = threadIdx.x & 31;
    int b = w / 768, o = w - b * 768;
    const float* wr = qkv_w + (size_t)o * 256;
    const float* be = g_beta + b * 256;
    float acc = 0.f;
#pragma unroll
    for (int c = lane; c < 256; c += 32) acc += wr[c] * be[c];
#pragma unroll
    for (int off = 16; off > 0; off >>= 1) acc += __shfl_xor_sync(0xffffffffu, acc, off);
    if (lane == 0) g_bb[w] = acc + qkv_b[o];
}

// ---------------------------------------------------------------------------
// Weight pre-pack: blob [ob][kc][row][16] of c-pair f16x2, hi+lo planes.
// ---------------------------------------------------------------------------
__global__ void __launch_bounds__(256) k_packw(const float* __restrict__ W,
                                               uint32_t* __restrict__ Ah,
                                               uint32_t* __restrict__ Al) {
    int idx = blockIdx.x * 256 + threadIdx.x;
    int ob  = idx >> 14;
    int rem = idx & 16383;
    int kc  = rem >> 11;
    int row = (rem >> 4) & 127;
    int wd  = rem & 15;
    int o = ob * 128 + row;
    int c = kc * 32 + 2 * wd;
    uint32_t h, l;
    pack2(W[(size_t)o * 256 + c], W[(size_t)o * 256 + c + 1], h, l);
    Ah[idx] = h;
    Al[idx] = l;
}

// X pre-pack: alpha-scaled c-pairs, hi only. [b][c2][n]
__global__ void __launch_bounds__(256) k_packx() {
    int idx = blockIdx.x * 256 + threadIdx.x;
    int b  = idx >> 18;
    int c2 = (idx >> 11) & 127;
    int n  = idx & 2047;
    float a0 = g_alpha[b * 256 + 2 * c2];
    float a1 = g_alpha[b * 256 + 2 * c2 + 1];
    float v0 = g_xr[((size_t)(b * 256 + 2 * c2)) * NTOK + n] * a0;
    float v1 = g_xr[((size_t)(b * 256 + 2 * c2 + 1)) * NTOK + n] * a1;
    g_xp[idx] = pack_h(v0, v1);
}

// ---------------------------------------------------------------------------
// GEMM on pre-packed operands. A from blob (hi/lo), B packed hi.
// split=1: epilogue routes to g_qp/g_kp/g_vp.
// ---------------------------------------------------------------------------
#define GAS 20
#define GBS 136
#define STGS 66
#define GEMM_SMEM (128 * STGS * 4 > (2 * 128 * GAS + 16 * GBS) * 4 ? \
                   128 * STGS * 4 : (2 * 128 * GAS + 16 * GBS) * 4)

__global__ void __launch_bounds__(256, 2) k_gemm_p(
    const uint32_t* __restrict__ Ah, const uint32_t* __restrict__ Al,
    const uint32_t* __restrict__ Bp, const float* __restrict__ bias,
    int M, int biasPerBatch, float* __restrict__ out, int split)
{
    extern __shared__ uint32_t sg[];
    uint32_t* ApH = sg;
    uint32_t* ApL = ApH + 128 * GAS;
    uint32_t* BpH = ApL + 128 * GAS;

    int n0 = blockIdx.x * 128, ob = blockIdx.y, bb = blockIdx.z;
    int o0 = ob * 128;
    int tid = threadIdx.x, lane = tid & 31, wid = tid >> 5;
    int wm = wid >> 2, wn = wid & 3;
    int lq = lane >> 2, lr = lane & 3;

    float acc[4][4][4];
#pragma unroll
    for (int i = 0; i < 4; i++)
#pragma unroll
        for (int j = 0; j < 4; j++)
#pragma unroll
            for (int r = 0; r < 4; r++) acc[i][j][r] = 0.f;

    int arow = tid >> 1, aoff = (tid & 1) * 8;
    for (int kc = 0; kc < 8; kc++) {
        __syncthreads();
        // A tile: straight copy from blob image
        {
            const uint32_t* ab = Ah + ((size_t)(ob * 8 + kc)) * 2048 + tid * 8;
            const uint32_t* al = Al + ((size_t)(ob * 8 + kc)) * 2048 + tid * 8;
            uint4 h0 = *(const uint4*)(ab);
            uint4 h1 = *(const uint4*)(ab + 4);
            uint4 l0 = *(const uint4*)(al);
            uint4 l1 = *(const uint4*)(al + 4);
            *(uint4*)(ApH + arow * GAS + aoff)     = h0;
            *(uint4*)(ApH + arow * GAS + aoff + 4) = h1;
            *(uint4*)(ApL + arow * GAS + aoff)     = l0;
            *(uint4*)(ApL + arow * GAS + aoff + 4) = l1;
        }
        // B tile: straight copy
#pragma unroll
        for (int r = 0; r < 2; r++) {
            int idx = tid + r * 256;
            int c2 = idx >> 5, n4 = (idx & 31) << 2;
            uint4 v = *(const uint4*)(Bp + ((size_t)(bb * 128 + kc * 16 + c2)) * NTOK + n0 + n4);
            *(uint4*)(BpH + c2 * GBS + n4) = v;
        }
        __syncthreads();

#pragma unroll
        for (int ks = 0; ks < 2; ks++) {
            uint32_t ah[4][4], al_[4][4];
#pragma unroll
            for (int mf = 0; mf < 4; mf++) {
                int m = wm * 64 + mf * 16 + lq;
                int r0 = m * GAS + ks * 8 + lr;
                int r1 = r0 + 4;
                ah[mf][0] = ApH[r0]; ah[mf][1] = ApH[r0 + 8 * GAS];
                ah[mf][2] = ApH[r1]; ah[mf][3] = ApH[r1 + 8 * GAS];
                al_[mf][0] = ApL[r0]; al_[mf][1] = ApL[r0 + 8 * GAS];
                al_[mf][2] = ApL[r1]; al_[mf][3] = ApL[r1 + 8 * GAS];
            }
#pragma unroll
            for (int nf = 0; nf < 4; nf++) {
                int n = wn * 32 + nf * 8 + lq;
                int b0i = (ks * 8 + lr) * GBS + n;
                int b1i = (ks * 8 + 4 + lr) * GBS + n;
                uint32_t bh[2] = {BpH[b0i], BpH[b1i]};
#pragma unroll
                for (int mf = 0; mf < 4; mf++) {
                    mma16(acc[mf][nf], ah[mf], bh);
                    mma16(acc[mf][nf], al_[mf], bh);
                }
            }
        }
    }

    if (split) {
        uint32_t* stg = sg;   // [128 rows][STGS]
        __syncthreads();
#pragma unroll
        for (int mf = 0; mf < 4; mf++) {
#pragma unroll
            for (int rr = 0; rr < 2; rr++) {
                int o = o0 + wm * 64 + mf * 16 + lq + rr * 8;
                int h = o / 192, rm = o - h * 192;
                float bv = bias[bb * 768 + o];
                float scl = (rm < 64) ? QSCALE : 1.f;
                size_t hb = (size_t)(bb * 4 + h);
#pragma unroll
                for (int nf = 0; nf < 4; nf++) {
                    int n = n0 + wn * 32 + nf * 8 + 2 * lr;
                    float v0 = (acc[mf][nf][rr * 2 + 0] + bv) * scl;
                    float v1 = (acc[mf][nf][rr * 2 + 1] + bv) * scl;
                    uint32_t pk = pack_h(v0, v1);
                    if (rm >= 128) {
                        g_vp[(hb * 64 + (rm - 128)) * (NTOK / 2) + (n >> 1)] = pk;
                    } else {
                        stg[(o - o0) * STGS + ((n - n0) >> 1)] = pk;
                    }
                }
            }
        }
        __syncthreads();
#pragma unroll
        for (int i = 0; i < 16; i++) {
            int idx = tid + i * 256;
            int c2l = idx >> 6, n2 = idx & 63;
            int o = o0 + 2 * c2l;
            int h = o / 192, rm = o - h * 192;
            if (rm < 128) {
                uint32_t s0v = stg[(2 * c2l) * STGS + n2];
                uint32_t s1v = stg[(2 * c2l + 1) * STGS + n2];
                uint32_t e0 = __byte_perm(s0v, s1v, 0x5410);
                uint32_t e1 = __byte_perm(s0v, s1v, 0x7632);
                size_t hb = (size_t)(bb * 4 + h);
                uint32_t* dst = (rm < 64) ? g_qp : g_kp;
                int c2g = (rm < 64 ? rm : rm - 64) >> 1;
                *(uint2*)(dst + (hb * 32 + c2g) * NTOK + n0 + 2 * n2) = make_uint2(e0, e1);
            }
        }
    } else {
#pragma unroll
        for (int mf = 0; mf < 4; mf++) {
            int o = o0 + wm * 64 + mf * 16 + lq;
            float b0 = biasPerBatch ? bias[bb * M + o] : bias[o];
            float b1 = biasPerBatch ? bias[bb * M + o + 8] : bias[o + 8];
#pragma unroll
            for (int nf = 0; nf < 4; nf++) {
                int n = n0 + wn * 32 + nf * 8 + 2 * lr;
                float2 v0 = make_float2(acc[mf][nf][0] + b0, acc[mf][nf][1] + b0);
                float2 v1 = make_float2(acc[mf][nf][2] + b1, acc[mf][nf][3] + b1);
                *(float2*)(out + ((size_t)bb * M + o) * NTOK + n) = v0;
                *(float2*)(out + ((size_t)bb * M + o + 8) * NTOK + n) = v1;
            }
        }
    }
}

// ---------------------------------------------------------------------------
// Attention (fp16, pre-packed). Q fragments hoisted to registers.
// S = QK (1 MMA, log2-domain); P = f16(ex2(S)); O^T = P x V (1 MMA).
// Epilogue writes packed c-pair f16x2 to g_ap.
// ---------------------------------------------------------------------------
#define QKS 136
#define VS2 68
#define PS2 68
#define PFP 136
#define ATT_SMEM ((2 * 32 * QKS + 64 * VS2 + 128 * PS2) * 4 + 512)

__global__ void __launch_bounds__(256, 2) k_attn_b() {
    extern __shared__ uint32_t su[];
    uint32_t* QpH = su;                    // [32 c2][QKS t]
    uint32_t* KpH = QpH + 32 * QKS;        // [32 c2][QKS s]
    uint32_t* VpH = KpH + 32 * QKS;        // [64 c][VS2 s2]
    uint32_t* PsH = VpH + 64 * VS2;        // [128 t][PS2 s2]
    float*    Ls  = (float*)(PsH + 128 * PS2);

    int hb = blockIdx.x >> 4, qt = blockIdx.x & 15;
    const uint32_t* qp = g_qp + (size_t)hb * 32 * NTOK;
    const uint32_t* kp = g_kp + (size_t)hb * 32 * NTOK;
    const uint32_t* vp = g_vp + (size_t)hb * 64 * (NTOK / 2);
    int tid = threadIdx.x, lane = tid & 31, wid = tid >> 5;
    int wt = wid >> 1, ws = wid & 1;
    int lq = lane >> 2, lr = lane & 3;
    int t0 = qt * 128;

    if (tid < 128) Ls[tid] = 0.f;

    // Q tile -> smem, then hoist fragments to registers
#pragma unroll
    for (int r = 0; r < 4; r++) {
        int idx = tid + r * 256;
        int c2 = idx >> 5, t4 = (idx & 31) << 2;
        uint4 v = *(const uint4*)(qp + c2 * NTOK + t0 + t4);
        *(uint4*)(QpH + c2 * QKS + t4) = v;
    }
    __syncthreads();

    uint32_t qf[4][2][4];
#pragma unroll
    for (int ks = 0; ks < 4; ks++)
#pragma unroll
        for (int mf = 0; mf < 2; mf++) {
            int t = wt * 32 + mf * 16 + lq;
            int r0 = (ks * 8 + lr) * QKS + t;
            int r1 = (ks * 8 + 4 + lr) * QKS + t;
            qf[ks][mf][0] = QpH[r0]; qf[ks][mf][1] = QpH[r0 + 8];
            qf[ks][mf][2] = QpH[r1]; qf[ks][mf][3] = QpH[r1 + 8];
        }

    float accO[8][4];
#pragma unroll
    for (int i = 0; i < 8; i++)
#pragma unroll
        for (int r = 0; r < 4; r++) accO[i][r] = 0.f;
    float lsum[4] = {0.f, 0.f, 0.f, 0.f};

    for (int st = 0; st < 16; st++) {
        int s0 = st * 128;
#pragma unroll
        for (int r = 0; r < 4; r++) {
            int idx = tid + r * 256;
            int c2 = idx >> 5, s4 = (idx & 31) << 2;
            uint4 v = *(const uint4*)(kp + c2 * NTOK + s0 + s4);
            *(uint4*)(KpH + c2 * QKS + s4) = v;
        }
#pragma unroll
        for (int r = 0; r < 4; r++) {
            int idx = tid + r * 256;
            int c = idx >> 4, s2q = (idx & 15) << 2;
            uint4 v = *(const uint4*)(vp + c * (NTOK / 2) + (s0 >> 1) + s2q);
            *(uint2*)(VpH + c * VS2 + s2q)     = make_uint2(v.x, v.y);
            *(uint2*)(VpH + c * VS2 + s2q + 2) = make_uint2(v.z, v.w);
        }
        __syncthreads();

        // ------- phase 1: S = Q^T K, two 32-column halves per warp -------
#pragma unroll
        for (int half = 0; half < 2; half++) {
            float accS[2][4][4];
#pragma unroll
            for (int i = 0; i < 2; i++)
#pragma unroll
                for (int j = 0; j < 4; j++)
#pragma unroll
                    for (int r = 0; r < 4; r++) accS[i][j][r] = 0.f;

#pragma unroll
            for (int ks = 0; ks < 4; ks++) {
#pragma unroll
                for (int nf = 0; nf < 4; nf++) {
                    int s = ws * 64 + half * 32 + nf * 8 + lq;
                    int b0i = (ks * 8 + lr) * QKS + s;
                    int b1i = (ks * 8 + 4 + lr) * QKS + s;
                    uint32_t bh[2] = {KpH[b0i], KpH[b1i]};
#pragma unroll
                    for (int mf = 0; mf < 2; mf++)
                        mma16(accS[mf][nf], qf[ks][mf], bh);
                }
            }

#pragma unroll
            for (int mf = 0; mf < 2; mf++) {
                int t = wt * 32 + mf * 16 + lq;
#pragma unroll
                for (int nf = 0; nf < 4; nf++) {
                    int s2 = ws * 32 + half * 16 + nf * 4 + lr;
                    float e0 = ex2(accS[mf][nf][0]);
                    float e1 = ex2(accS[mf][nf][1]);
                    float e2 = ex2(accS[mf][nf][2]);
                    float e3 = ex2(accS[mf][nf][3]);
                    lsum[mf * 2 + 0] += e0 + e1;
                    lsum[mf * 2 + 1] += e2 + e3;
                    PsH[t * PS2 + s2]       = pack_h(e0, e1);
                    PsH[(t + 8) * PS2 + s2] = pack_h(e2, e3);
                }
            }
        }
        __syncthreads();

        // ------- phase 2: O^T[t][c] += P[t][s] * V[c][s] (1 MMA) -------
        int tb = wid * 16 + lq;
#pragma unroll
        for (int ks = 0; ks < 8; ks++) {
            int p0 = tb * PS2 + ks * 8 + lr;
            uint32_t ah[4];
            ah[0] = PsH[p0];     ah[1] = PsH[p0 + 8 * PS2];
            ah[2] = PsH[p0 + 4]; ah[3] = PsH[p0 + 8 * PS2 + 4];
#pragma unroll
            for (int nf = 0; nf < 8; nf++) {
                int c = nf * 8 + lq;
                int b0i = c * VS2 + ks * 8 + lr;
                uint32_t bh[2] = {VpH[b0i], VpH[b0i + 4]};
                mma16(accO[nf], ah, bh);
            }
        }
        __syncthreads();
    }

    // reduce row sums into Ls
#pragma unroll
    for (int i = 0; i < 4; i++) {
        lsum[i] += __shfl_xor_sync(0xffffffffu, lsum[i], 1);
        lsum[i] += __shfl_xor_sync(0xffffffffu, lsum[i], 2);
    }
    if (lr == 0) {
        atomicAdd(&Ls[wt * 32 + lq],          lsum[0]);
        atomicAdd(&Ls[wt * 32 + lq + 8],      lsum[1]);
        atomicAdd(&Ls[wt * 32 + 16 + lq],     lsum[2]);
        atomicAdd(&Ls[wt * 32 + 16 + lq + 8], lsum[3]);
    }
    __syncthreads();

    // normalize + transpose via float scratch (overwrites Q/K tiles)
    float* Pf = (float*)su;    // [64 c][PFP t]
    float inv0 = 1.f / Ls[wid * 16 + lq];
    float inv1 = 1.f / Ls[wid * 16 + lq + 8];
    int t = wid * 16 + lq;
#pragma unroll
    for (int nf = 0; nf < 8; nf++) {
        int cc = nf * 8 + 2 * lr;
        Pf[cc * PFP + t]           = accO[nf][0] * inv0;
        Pf[(cc + 1) * PFP + t]     = accO[nf][1] * inv0;
        Pf[cc * PFP + t + 8]       = accO[nf][2] * inv1;
        Pf[(cc + 1) * PFP + t + 8] = accO[nf][3] * inv1;
    }
    __syncthreads();

    // pack c-pairs -> g_ap [b][c2][t]
    int bb = hb >> 2;
    int cbase = (hb & 3) * 32;
#pragma unroll
    for (int r = 0; r < 4; r++) {
        int idx = tid + r * 256;
        int c2l = idx >> 5, t4 = (idx & 31) << 2;
        uint32_t w0 = pack_h(Pf[(2 * c2l) * PFP + t4],     Pf[(2 * c2l + 1) * PFP + t4]);
        uint32_t w1 = pack_h(Pf[(2 * c2l) * PFP + t4 + 1], Pf[(2 * c2l + 1) * PFP + t4 + 1]);
        uint32_t w2 = pack_h(Pf[(2 * c2l) * PFP + t4 + 2], Pf[(2 * c2l + 1) * PFP + t4 + 2]);
        uint32_t w3 = pack_h(Pf[(2 * c2l) * PFP + t4 + 3], Pf[(2 * c2l + 1) * PFP + t4 + 3]);
        *(uint4*)(g_ap + ((size_t)(bb * 128 + cbase + c2l)) * NTOK + t0 + t4) =
            make_uint4(w0, w1, w2, w3);
    }
}

// ---------------------------------------------------------------------------
// Inverse FFT2
// ---------------------------------------------------------------------------
__global__ void __launch_bounds__(32) k_ifft(float* __restrict__ outp) {
    __shared__ float sr[32][33];
    __shared__ float si[32][33];
    __shared__ float2 tw[32];

    int img  = blockIdx.x;
    int lane = threadIdx.x;

    float sn, cs;
    __sincosf(6.283185307179586f * (float)lane / 32.f, &sn, &cs);
    tw[lane] = make_float2(cs, sn);

    const float* ip = g_proj + (size_t)img * NTOK;
#pragma unroll
    for (int y = 0; y < 32; y++) {
        sr[y][lane] = ip[(y * 32 + lane) * 2 + 0];
        si[y][lane] = ip[(y * 32 + lane) * 2 + 1];
    }
    __syncwarp();

    float cr[32], ci[32];
#pragma unroll
    for (int j = 0; j < 32; j++) { cr[j] = sr[lane][j]; ci[j] = si[lane][j]; }
    __syncwarp();

    for (int k = 0; k < 32; k++) {
        float ar = 0.f, ai = 0.f;
#pragma unroll
        for (int j = 0; j < 32; j++) {
            float2 w = tw[(j * k) & 31];
            ar += cr[j] * w.x - ci[j] * w.y;
            ai += cr[j] * w.y + ci[j] * w.x;
        }
        sr[k][lane] = ar;
        si[k][lane] = ai;
    }
    __syncwarp();

#pragma unroll
    for (int j = 0; j < 32; j++) { cr[j] = sr[lane][j]; ci[j] = si[lane][j]; }

    float* op = outp + (size_t)img * NTOK;
    for (int k = 0; k < 32; k++) {
        float ar = 0.f, ai = 0.f;
#pragma unroll
        for (int j = 0; j < 32; j++) {
            float2 w = tw[(j * k) & 31];
            ar += cr[j] * w.x - ci[j] * w.y;
            ai += cr[j] * w.y + ci[j] * w.x;
        }
        op[(k * 32 + lane) * 2 + 0] = ar * (1.f / 1024.f);
        op[(k * 32 + lane) * 2 + 1] = ai * (1.f / 1024.f);
    }
}

// ---------------------------------------------------------------------------
extern "C" void kernel_launch(void* const* d_in, const int* in_sizes, int n_in,
                              void* d_out, int out_size) {
    const float* x      = (const float*)d_in[0];
    const float* gn_w   = (const float*)d_in[1];
    const float* gn_b   = (const float*)d_in[2];
    const float* qkv_w  = (const float*)d_in[3];
    const float* qkv_b  = (const float*)d_in[4];
    const float* proj_w = (const float*)d_in[5];
    const float* proj_b = (const float*)d_in[6];
    float* out = (float*)d_out;

    float *p_proj, *p_bb;
    uint32_t *p_wqh, *p_wql, *p_wph, *p_wpl, *p_xp, *p_ap;
    cudaGetSymbolAddress((void**)&p_proj, g_proj);
    cudaGetSymbolAddress((void**)&p_bb,   g_bb);
    cudaGetSymbolAddress((void**)&p_wqh,  g_wqh);
    cudaGetSymbolAddress((void**)&p_wql,  g_wql);
    cudaGetSymbolAddress((void**)&p_wph,  g_wph);
    cudaGetSymbolAddress((void**)&p_wpl,  g_wpl);
    cudaGetSymbolAddress((void**)&p_xp,   g_xp);
    cudaGetSymbolAddress((void**)&p_ap,   g_ap);

    cudaFuncSetAttribute(k_attn_b, cudaFuncAttributeMaxDynamicSharedMemorySize, ATT_SMEM);
    cudaFuncSetAttribute(k_gemm_p, cudaFuncAttributeMaxDynamicSharedMemorySize, GEMM_SMEM);

    k_zero_stats<<<1, 512>>>();
    k_fft<<<2048, 32>>>(x);
    k_prep_ab<<<8, 256>>>(gn_w, gn_b);
    k_packw<<<384, 256>>>(qkv_w, p_wqh, p_wql);
    k_packw<<<128, 256>>>(proj_w, p_wph, p_wpl);
    k_prep_bb<<<768, 256>>>(qkv_w, qkv_b);
    k_packx<<<8192, 256>>>();
    k_gemm_p<<<dim3(16, 6, 8), 256, GEMM_SMEM>>>(p_wqh, p_wql, p_xp, p_bb, 768, 1,
                                                 nullptr, 1);
    k_attn_b<<<512, 256, ATT_SMEM>>>();
    k_gemm_p<<<dim3(16, 2, 8), 256, GEMM_SMEM>>>(p_wph, p_wpl, p_ap, proj_b, 256, 0,
                                                 p_proj, 0);
    k_ifft<<<2048, 32>>>(out);
}